// round 6
// baseline (speedup 1.0000x reference)
#include <cuda_runtime.h>
#include <cuda_fp16.h>
#include <math.h>

#define BB 16
#define HH 12
#define NN 784
#define NROWS (BB * NN)          // 12544
#define NSQ (NN * NN)            // 614656
#define NWS (NROWS * HH)         // 150528 per-warp stats

// Device-global scratch (allocation is forbidden; __device__ globals are allowed)
__device__ __half g_scratch[(size_t)BB * NSQ];   // exp(a - M_w), ~19.7 MB
__device__ float2 g_warpstats[NWS];              // (warp max, warp sumexp)
__device__ float  g_warpscale[NWS];              // exp(M_w - gmax) / sum_b

// ---------------------------------------------------------------------------
// k_agg: one block per (b,i). 384 threads = 12 warps, warp w stages head w's
// row in SMEM (+ rowsum). After ONE barrier, each thread computes its
// aggregated values a[l] = sum_h m[h][l]*rs[h]; each warp then uses its OWN
// max M_w as softmax shift (valid: stored exp(a-M_w) <= 1, corrected later by
// the per-(row,segment) scale), so no cross-warp reductions or broadcasts are
// needed. Lane 0 writes (M_w, sumexp_w) straight to global.
// Input loads use __ldcs so the touch-once 472 MB stream doesn't evict the
// L2-resident scratch (proven win in R5).
// ---------------------------------------------------------------------------
__global__ __launch_bounds__(384, 5) void k_agg(const float* __restrict__ m) {
    __shared__ float sm[HH * NN];   // 37632 B
    __shared__ float rs[HH];

    const int bi = blockIdx.x;          // b*NN + i
    const int b  = bi / NN;
    const int i  = bi - b * NN;
    const int t    = threadIdx.x;
    const int w    = t >> 5;
    const int lane = t & 31;

    // stage head-w row (196 float4s, evict-first) + rowsum
    const float4* row = (const float4*)(m + ((size_t)(b * HH + w) * NN + i) * NN);
    float4* smrow = (float4*)(sm + w * NN);
    float s = 0.f;
    #pragma unroll
    for (int j = lane; j < NN / 4; j += 32) {
        float4 v = __ldcs(row + j);
        smrow[j] = v;
        s += (v.x + v.y) + (v.z + v.w);
    }
    #pragma unroll
    for (int o = 16; o; o >>= 1) s += __shfl_xor_sync(0xffffffffu, s, o);
    if (lane == 0) rs[w] = s;
    __syncthreads();                      // the ONLY barrier

    float rr[HH];
    #pragma unroll
    for (int h = 0; h < HH; h++) rr[h] = rs[h];

    // aggregated values: thread t owns l = t, t+384, and (t<16) t+768
    float a0 = 0.f, a1 = 0.f, a2 = -INFINITY;
    #pragma unroll
    for (int h = 0; h < HH; h++) {
        a0 = fmaf(sm[h * NN + t],       rr[h], a0);
        a1 = fmaf(sm[h * NN + t + 384], rr[h], a1);
    }
    const bool tail = (t < 16);
    if (tail) {
        a2 = 0.f;
        #pragma unroll
        for (int h = 0; h < HH; h++) a2 = fmaf(sm[h * NN + t + 768], rr[h], a2);
    }

    // per-warp max (l range [768,784) belongs to warp 0 -> consistent segments)
    float mx = fmaxf(fmaxf(a0, a1), a2);
    #pragma unroll
    for (int o = 16; o; o >>= 1) mx = fmaxf(mx, __shfl_xor_sync(0xffffffffu, mx, o));

    // exp + fp16 store + warp expsum
    __half* srow = g_scratch + (size_t)bi * NN;
    float e0 = __expf(a0 - mx);
    float e1 = __expf(a1 - mx);
    srow[t]       = __float2half_rn(e0);
    srow[t + 384] = __float2half_rn(e1);
    float sume = e0 + e1;
    if (tail) {
        float e2 = __expf(a2 - mx);
        srow[t + 768] = __float2half_rn(e2);
        sume += e2;
    }
    #pragma unroll
    for (int o = 16; o; o >>= 1) sume += __shfl_xor_sync(0xffffffffu, sume, o);
    if (lane == 0) g_warpstats[bi * HH + w] = make_float2(mx, sume);
}

// ---------------------------------------------------------------------------
// k_combine: one block per batch, 512 threads. Reduce 784*12 warp stats ->
// gmax, 1/sum; write per-(row,segment) scales. All data L2-resident (~1.2 MB).
// Fixed-order reductions -> deterministic.
// ---------------------------------------------------------------------------
__global__ __launch_bounds__(512) void k_combine() {
    const int b = blockIdx.x;
    const int t = threadIdx.x;
    const float2* st = g_warpstats + b * NN * HH;   // 9408 entries
    __shared__ float red[16];
    __shared__ float s_gmax, s_inv;

    // phase 1: gmax
    float mx = -INFINITY;
    for (int k = t; k < NN * HH; k += 512) mx = fmaxf(mx, st[k].x);
    #pragma unroll
    for (int o = 16; o; o >>= 1) mx = fmaxf(mx, __shfl_xor_sync(0xffffffffu, mx, o));
    if ((t & 31) == 0) red[t >> 5] = mx;
    __syncthreads();
    if (t == 0) {
        float M = red[0];
        #pragma unroll
        for (int k = 1; k < 16; k++) M = fmaxf(M, red[k]);
        s_gmax = M;
    }
    __syncthreads();
    const float gmax = s_gmax;

    // phase 2: sum = sum_k sume_k * exp(M_k - gmax)
    float s = 0.f;
    for (int k = t; k < NN * HH; k += 512) {
        float2 v = st[k];
        s += v.y * __expf(v.x - gmax);
    }
    #pragma unroll
    for (int o = 16; o; o >>= 1) s += __shfl_xor_sync(0xffffffffu, s, o);
    __syncthreads();                   // protect red[] reuse
    if ((t & 31) == 0) red[t >> 5] = s;
    __syncthreads();
    if (t == 0) {
        float S = 0.f;
        #pragma unroll
        for (int k = 0; k < 16; k++) S += red[k];
        s_inv = 1.f / S;
    }
    __syncthreads();
    const float inv = s_inv;

    // phase 3: per-(row,segment) scale
    for (int k = t; k < NN * HH; k += 512)
        g_warpscale[b * NN * HH + k] = __expf(st[k].x - gmax) * inv;
}

// ---------------------------------------------------------------------------
// k_norm: out[row][l] = half2float(scratch[row][l]) * warpscale[row][seg(l)]
// seg(l) = (l % 384)/32 for l < 768, else 0 (matches k_agg thread mapping;
// all 8 halves of an int4 share one segment since l0 is a multiple of 8).
// Total int4 = 16*614656/8 = 1,229,312 = 4802 blocks * 256 exactly.
// ---------------------------------------------------------------------------
__global__ __launch_bounds__(256) void k_norm(float* __restrict__ out) {
    const int j   = blockIdx.x * 256 + threadIdx.x;   // int4 index
    const int row = j / 98;                            // 98 int4 per row
    const int jm  = j - row * 98;                      // 0..97
    const int seg = (jm < 96) ? ((jm % 48) >> 2) : 0;  // l0=jm*8; (l0%384)/32
    const float sc = g_warpscale[row * HH + seg];

    int4 v = ((const int4*)g_scratch)[j];
    float2 f0 = __half22float2(*(__half2*)&v.x);
    float2 f1 = __half22float2(*(__half2*)&v.y);
    float2 f2 = __half22float2(*(__half2*)&v.z);
    float2 f3 = __half22float2(*(__half2*)&v.w);

    float4 o0 = make_float4(f0.x * sc, f0.y * sc, f1.x * sc, f1.y * sc);
    float4 o1 = make_float4(f2.x * sc, f2.y * sc, f3.x * sc, f3.y * sc);
    ((float4*)out)[2 * j]     = o0;
    ((float4*)out)[2 * j + 1] = o1;
}

// ---------------------------------------------------------------------------
extern "C" void kernel_launch(void* const* d_in, const int* in_sizes, int n_in,
                              void* d_out, int out_size) {
    const float* m = (const float*)d_in[0];
    float* out = (float*)d_out;

    k_agg<<<NROWS, 384>>>(m);
    k_combine<<<BB, 512>>>();
    k_norm<<<4802, 256>>>(out);
}

// round 7
// speedup vs baseline: 1.4506x; 1.4506x over previous
#include <cuda_runtime.h>
#include <cuda_fp16.h>
#include <math.h>

#define BB 16
#define HH 12
#define NN 784
#define NROWS (BB * NN)        // 12544
#define NSQ (NN * NN)          // 614656
#define JPB (NSQ / 8)          // int4 chunks per batch = 76832
#define NORM_BX 301            // ceil(76832/256)

// Device-global scratch (allocation is forbidden; __device__ globals are allowed)
__device__ __half g_scratch[(size_t)BB * NSQ];   // exp(x - rowmax), ~19.7 MB
__device__ float2 g_rowstats[NROWS];             // (rowmax, rowsumexp)

// ---------------------------------------------------------------------------
// k_agg: EXACT R5-proven version (80.3us, 6.07 TB/s). One block per (b,i);
// 12 warps stage the 12 head rows in SMEM (+rowsums), block computes
// agg[l] = sum_h m[h][l]*rowsum[h], row max, exp (fp16 to scratch), row
// expsum, and writes per-row stats. Input loads __ldcs so the touch-once
// 472 MB stream doesn't evict the L2-resident scratch.
// ---------------------------------------------------------------------------
__global__ __launch_bounds__(384) void k_agg(const float* __restrict__ m) {
    __shared__ float sm[HH * NN];   // 37632 B
    __shared__ float rs[HH];
    __shared__ float red[HH];
    __shared__ float s_bcast;

    const int bi = blockIdx.x;          // b*NN + i
    const int b  = bi / NN;
    const int i  = bi - b * NN;
    const int t    = threadIdx.x;
    const int w    = t >> 5;
    const int lane = t & 31;

    const float4* row = (const float4*)(m + ((size_t)(b * HH + w) * NN + i) * NN);
    float4* smrow = (float4*)(sm + w * NN);
    float s = 0.f;
    #pragma unroll
    for (int j = lane; j < NN / 4; j += 32) {
        float4 v = __ldcs(row + j);
        smrow[j] = v;
        s += (v.x + v.y) + (v.z + v.w);
    }
    #pragma unroll
    for (int o = 16; o; o >>= 1) s += __shfl_xor_sync(0xffffffffu, s, o);
    if (lane == 0) rs[w] = s;
    __syncthreads();

    float rr[HH];
    #pragma unroll
    for (int h = 0; h < HH; h++) rr[h] = rs[h];

    float a0 = 0.f, a1 = 0.f, a2 = 0.f;
    #pragma unroll
    for (int h = 0; h < HH; h++) {
        a0 = fmaf(sm[h * NN + t],       rr[h], a0);
        a1 = fmaf(sm[h * NN + t + 384], rr[h], a1);
    }
    if (t < 16) {
        #pragma unroll
        for (int h = 0; h < HH; h++) a2 = fmaf(sm[h * NN + t + 768], rr[h], a2);
    }

    float mx = fmaxf(a0, a1);
    if (t < 16) mx = fmaxf(mx, a2);
    #pragma unroll
    for (int o = 16; o; o >>= 1) mx = fmaxf(mx, __shfl_xor_sync(0xffffffffu, mx, o));
    if (lane == 0) red[w] = mx;
    __syncthreads();
    if (t == 0) {
        float M = red[0];
        #pragma unroll
        for (int h = 1; h < HH; h++) M = fmaxf(M, red[h]);
        s_bcast = M;
    }
    __syncthreads();
    const float rowmax = s_bcast;

    __half* srow = g_scratch + (size_t)bi * NN;
    float e0 = expf(a0 - rowmax);
    float e1 = expf(a1 - rowmax);
    srow[t]       = __float2half_rn(e0);
    srow[t + 384] = __float2half_rn(e1);
    float sume = e0 + e1;
    if (t < 16) {
        float e2 = expf(a2 - rowmax);
        srow[t + 768] = __float2half_rn(e2);
        sume += e2;
    }
    #pragma unroll
    for (int o = 16; o; o >>= 1) sume += __shfl_xor_sync(0xffffffffu, sume, o);
    if (lane == 0) red[w] = sume;
    __syncthreads();
    if (t == 0) {
        float S = 0.f;
        #pragma unroll
        for (int h = 0; h < HH; h++) S += red[h];
        g_rowstats[bi] = make_float2(rowmax, S);
    }
}

// ---------------------------------------------------------------------------
// k_norm (combine fused in): grid = (301, 16). Each block first redundantly
// reduces its batch's 784 row-stats (L2-resident, identical fixed order in
// every block -> deterministic) into (gmax, 1/sum), then streams its 256 int4
// chunks: out = half2float(scratch) * exp(rowmax-gmax)/sum. Out stores are
// __stcs (touch-once; keep L2 for scratch).
// ---------------------------------------------------------------------------
__global__ __launch_bounds__(256) void k_norm(float* __restrict__ out) {
    const int b = blockIdx.y;
    const int t = threadIdx.x;
    const float2* st = g_rowstats + b * NN;
    __shared__ float red[8];
    __shared__ float s_gmax, s_inv;

    // phase 1: gmax over 784 row maxes
    float mx = -1e30f;
    #pragma unroll
    for (int i = t; i < NN; i += 256) mx = fmaxf(mx, st[i].x);
    #pragma unroll
    for (int o = 16; o; o >>= 1) mx = fmaxf(mx, __shfl_xor_sync(0xffffffffu, mx, o));
    if ((t & 31) == 0) red[t >> 5] = mx;
    __syncthreads();
    if (t == 0) {
        float M = red[0];
        #pragma unroll
        for (int k = 1; k < 8; k++) M = fmaxf(M, red[k]);
        s_gmax = M;
    }
    __syncthreads();
    const float gmax = s_gmax;

    // phase 2: sum = sum_i rowsumexp_i * exp(rowmax_i - gmax)
    float s = 0.f;
    #pragma unroll
    for (int i = t; i < NN; i += 256) {
        float2 v = st[i];
        s += v.y * __expf(v.x - gmax);
    }
    #pragma unroll
    for (int o = 16; o; o >>= 1) s += __shfl_xor_sync(0xffffffffu, s, o);
    __syncthreads();                  // protect red[] reuse
    if ((t & 31) == 0) red[t >> 5] = s;
    __syncthreads();
    if (t == 0) {
        float S = 0.f;
        #pragma unroll
        for (int k = 0; k < 8; k++) S += red[k];
        s_inv = 1.f / S;
    }
    __syncthreads();
    const float inv = s_inv;

    // phase 3: stream 8 halves -> 8 floats
    const int jb = blockIdx.x * 256 + t;           // chunk within batch
    if (jb >= JPB) return;
    const int lrow = jb / 98;                       // 98 int4 per row
    const float sc = __expf(st[lrow].x - gmax) * inv;

    const int j = b * JPB + jb;
    int4 v = ((const int4*)g_scratch)[j];
    float2 f0 = __half22float2(*(__half2*)&v.x);
    float2 f1 = __half22float2(*(__half2*)&v.y);
    float2 f2 = __half22float2(*(__half2*)&v.z);
    float2 f3 = __half22float2(*(__half2*)&v.w);

    float4 o0 = make_float4(f0.x * sc, f0.y * sc, f1.x * sc, f1.y * sc);
    float4 o1 = make_float4(f2.x * sc, f2.y * sc, f3.x * sc, f3.y * sc);
    __stcs(((float4*)out) + 2 * j,     o0);
    __stcs(((float4*)out) + 2 * j + 1, o1);
}

// ---------------------------------------------------------------------------
extern "C" void kernel_launch(void* const* d_in, const int* in_sizes, int n_in,
                              void* d_out, int out_size) {
    const float* m = (const float*)d_in[0];
    float* out = (float*)d_out;

    k_agg<<<NROWS, 384>>>(m);
    k_norm<<<dim3(NORM_BX, BB), 256>>>(out);
}